// round 14
// baseline (speedup 1.0000x reference)
#include <cuda_runtime.h>
#include <cuda_fp16.h>
#include <cstdint>
#include <math_constants.h>

#define Bb 2
#define Ll 256
#define Ee 512
#define Hh 8
#define QSCALE 0.125f

// ---------------- device scratch ----------------
__device__ float g_q[Bb*Ll*Ee];
__device__ float g_k[Bb*Ll*Ee];
__device__ float g_v[Bb*Ll*Ee];
__device__ float g_logits[(size_t)Bb*Hh*Ll*Ll];
__device__ float g_o1[Bb*Ll*Ee];
// fp16 (rne) copies; relation rows compacted in list order
__device__ __half g_rel_f16[(size_t)Bb*Ll*Ll*Ee];
__device__ __half g_w_f16[1024*512];   // [h*128+p][k]; p<64: Wrq rows, p>=64: Wrk rows
__device__ int g_cnt[Bb];
__device__ unsigned short g_list[Bb*Ll*Ll];

// ==================== PTX helpers ====================
__device__ __forceinline__ uint32_t smem_u32(const void* p) {
    uint32_t a;
    asm("{ .reg .u64 t; cvta.to.shared.u64 t, %1; cvt.u32.u64 %0, t; }" : "=r"(a) : "l"(p));
    return a;
}
#define SMEM_SWZ(o) ((o) ^ (((o) >> 3) & 0x70))
#define CP_ASYNC16(dst, src) \
    asm volatile("cp.async.cg.shared.global [%0], [%1], 16;" :: "r"(dst), "l"(src))
#define CP_COMMIT() asm volatile("cp.async.commit_group;" ::: "memory")
#define CP_WAIT1() asm volatile("cp.async.wait_group 1;" ::: "memory")
#define CP_WAIT0() asm volatile("cp.async.wait_group 0;" ::: "memory")

__device__ __forceinline__ void ldmx4(uint32_t& r0, uint32_t& r1, uint32_t& r2, uint32_t& r3, uint32_t addr) {
    asm volatile("ldmatrix.sync.aligned.m8n8.x4.shared.b16 {%0,%1,%2,%3}, [%4];"
        : "=r"(r0), "=r"(r1), "=r"(r2), "=r"(r3) : "r"(addr));
}
// m16n8k16 fp16 MMA, fp32 accumulate
__device__ __forceinline__ void mma_f16(float* c, const uint32_t* a, uint32_t b0, uint32_t b1) {
    asm volatile("mma.sync.aligned.m16n8k16.row.col.f32.f16.f16.f32 "
        "{%0,%1,%2,%3}, {%4,%5,%6,%7}, {%8,%9}, {%0,%1,%2,%3};"
        : "+f"(c[0]), "+f"(c[1]), "+f"(c[2]), "+f"(c[3])
        : "r"(a[0]), "r"(a[1]), "r"(a[2]), "r"(a[3]), "r"(b0), "r"(b1));
}

// ==================== split kernels (fp16 rne) ====================
__device__ __forceinline__ void cvt4_f16(float4 v, __half* dst) {
    __half2* d2 = (__half2*)dst;
    d2[0] = __floats2half2_rn(v.x, v.y);
    d2[1] = __floats2half2_rn(v.z, v.w);
}
__global__ void split_w_kernel(const float* __restrict__ Wr) {
    if (blockIdx.x == 0 && threadIdx.x < Bb) g_cnt[threadIdx.x] = 0;
    int r = blockIdx.x;                 // 0..1023
    int h = r >> 7, p = r & 127;
    int in_row = (p < 64) ? (h*64 + p) : (512 + h*64 + (p - 64));
    int t = threadIdx.x;                // 128 threads, 4 elems each
    float4 v = ((const float4*)(Wr + (size_t)in_row * 512))[t];
    cvt4_f16(v, g_w_f16 + (size_t)r * 512 + t * 4);
}

// ==================== double-buffered fp32 GEMM body ====================
// Y[m,n] = (sum_k X[m,k]*W[n,k] + bias[n]) * scale  for one 64x64 tile.
// Register prefetch of chunk kc+16 while chunk kc computes (hides LDG latency).
__device__ __forceinline__ void gemm64_db(const float* __restrict__ X,
                                          const float* __restrict__ W,
                                          const float* __restrict__ bias,
                                          float* __restrict__ Y,
                                          int m0, int n0, int Kdim, int Ndim,
                                          float scale,
                                          float Xs[16][64], float Ws[16][64])
{
    int tid = threadIdx.x;
    int ty = tid >> 4, tx = tid & 15;
    int r = tid >> 2, c4 = tid & 3;
    float acc[4][4];
#pragma unroll
    for (int a = 0; a < 4; a++)
#pragma unroll
        for (int bb = 0; bb < 4; bb++) acc[a][bb] = 0.f;

    float4 xv = *(const float4*)(X + (size_t)(m0 + r) * Kdim + c4 * 4);
    float4 wv = *(const float4*)(W + (size_t)(n0 + r) * Kdim + c4 * 4);
    for (int kc = 0; kc < Kdim; kc += 16) {
        __syncthreads();
        Xs[c4*4+0][r]=xv.x; Xs[c4*4+1][r]=xv.y; Xs[c4*4+2][r]=xv.z; Xs[c4*4+3][r]=xv.w;
        Ws[c4*4+0][r]=wv.x; Ws[c4*4+1][r]=wv.y; Ws[c4*4+2][r]=wv.z; Ws[c4*4+3][r]=wv.w;
        __syncthreads();
        if (kc + 16 < Kdim) {
            xv = *(const float4*)(X + (size_t)(m0 + r) * Kdim + kc + 16 + c4 * 4);
            wv = *(const float4*)(W + (size_t)(n0 + r) * Kdim + kc + 16 + c4 * 4);
        }
#pragma unroll
        for (int cc = 0; cc < 16; cc++) {
            float4 a = *(const float4*)&Xs[cc][ty*4];
            float4 bv4 = *(const float4*)&Ws[cc][tx*4];
            acc[0][0]+=a.x*bv4.x; acc[0][1]+=a.x*bv4.y; acc[0][2]+=a.x*bv4.z; acc[0][3]+=a.x*bv4.w;
            acc[1][0]+=a.y*bv4.x; acc[1][1]+=a.y*bv4.y; acc[1][2]+=a.y*bv4.z; acc[1][3]+=a.y*bv4.w;
            acc[2][0]+=a.z*bv4.x; acc[2][1]+=a.z*bv4.y; acc[2][2]+=a.z*bv4.z; acc[2][3]+=a.z*bv4.w;
            acc[3][0]+=a.w*bv4.x; acc[3][1]+=a.w*bv4.y; acc[3][2]+=a.w*bv4.z; acc[3][3]+=a.w*bv4.w;
        }
    }
#pragma unroll
    for (int rr = 0; rr < 4; rr++)
#pragma unroll
        for (int cc = 0; cc < 4; cc++)
            Y[(size_t)(m0+ty*4+rr) * Ndim + n0+tx*4+cc] = (acc[rr][cc] + bias[n0+tx*4+cc]) * scale;
}

// ==================== compact + qkv combo ====================
__global__ __launch_bounds__(256)
void compact_qkv_kernel(const int* __restrict__ adj,
                        const float* __restrict__ queries, const float* __restrict__ keys,
                        const float* __restrict__ values,
                        const float* __restrict__ Wq, const float* __restrict__ bq,
                        const float* __restrict__ Wk, const float* __restrict__ bk,
                        const float* __restrict__ Wv, const float* __restrict__ bv)
{
    if (blockIdx.x < 512) {
        int j = blockIdx.x & 255, b = blockIdx.x >> 8, i = threadIdx.x;
        int lane = i & 31, w = i >> 5;
        bool keep = adj[((size_t)(b * Ll + i)) * Ll + j] != 1;
        unsigned m = __ballot_sync(0xffffffffu, keep);
        int wpos = __popc(m & ((1u << lane) - 1));
        __shared__ int wcnt[8], wbase[9];
        if (lane == 0) wcnt[w] = __popc(m);
        __syncthreads();
        if (i == 0) {
            int s = 0;
            for (int x = 0; x < 8; x++) { wbase[x] = s; s += wcnt[x]; }
            wbase[8] = atomicAdd(&g_cnt[b], s);
        }
        __syncthreads();
        if (keep) g_list[b * (Ll*Ll) + wbase[8] + wbase[w] + wpos] = (unsigned short)((j << 8) | i);
        return;
    }
    int bid2 = blockIdx.x - 512;
    int z = bid2 >> 6, rem = bid2 & 63;
    const float* X = (z == 0) ? queries : (z == 1) ? keys : values;
    const float* W = (z == 0) ? Wq : (z == 1) ? Wk : Wv;
    const float* bias = (z == 0) ? bq : (z == 1) ? bk : bv;
    float* Y = (z == 0) ? g_q : (z == 1) ? g_k : g_v;
    const float scale = (z == 0) ? QSCALE : 1.0f;

    __shared__ float Xs[16][64];
    __shared__ float Ws[16][64];
    gemm64_db(X, W, bias, Y, (rem >> 3) * 64, (rem & 7) * 64, Ee, Ee, scale, Xs, Ws);
}

// Gather + fp16-round ONLY unmasked rel rows (compacted, list-ordered).
__global__ __launch_bounds__(256)
void split_rel_gather_kernel(const float* __restrict__ rel) {
    int b = blockIdx.y;
    int ent = blockIdx.x * 2 + (threadIdx.x >> 7);
    if (ent >= g_cnt[b]) return;
    int e = g_list[b * (Ll*Ll) + ent];
    int t = threadIdx.x & 127;
    float4 v = ((const float4*)(rel + ((size_t)(b * (Ll*Ll)) + e) * 512))[t];
    cvt4_f16(v, g_rel_f16 + ((size_t)(b * (Ll*Ll)) + ent) * 512 + t * 4);
}

// ==================== fp16 mma.sync relation attention ====================
// CTA = tile of 128 compacted pairs, 256 threads, occ 2.
// Single fp16 product (rne-prerounded; 10-bit mantissa == tf32).
// 64 kc-chunks of 64 halves (8 per head). Stage = A 16KB + B 16KB = 32KB;
// 3-deep ring (96KB), prefetch distance 2, cp.async interleaved into ks loop.
#define KSTG 32768
#define MMA_SMEM (3*KSTG)        // 98304

__global__ void __launch_bounds__(256, 2) rel_attn_mma_kernel()
{
    extern __shared__ char smem[];
    const uint32_t sb = smem_u32(smem);
    const int tid = threadIdx.x, lane = tid & 31, w = tid >> 5;
    const int wm = w & 3, wn = w >> 2;
    const int t = blockIdx.x, b = blockIdx.y;

    const int cnt = g_cnt[b];
    if (t * 128 >= cnt) return;
    const size_t rbase = (size_t)(b * (Ll*Ll)) + t * 128;
    const unsigned short* lst = g_list + b * (Ll*Ll);

    float c[2][8][4];
#pragma unroll
    for (int mt = 0; mt < 2; mt++)
#pragma unroll
        for (int g = 0; g < 8; g++)
#pragma unroll
            for (int e = 0; e < 4; e++) c[mt][g][e] = 0.f;

    auto issue_full = [&](int kc) {
        const int h = kc >> 3;
        const int kcol = (kc & 7) * 64;
        const uint32_t st = sb + (kc % 3) * KSTG;
        const __half* Bp = g_w_f16 + (size_t)h * 128 * 512;
#pragma unroll
        for (int r4 = 0; r4 < 4; r4++) {
            int idx = tid + r4 * 256;
            int row = idx >> 3, u = idx & 7;
            uint32_t so = SMEM_SWZ(row * 128 + u * 16);
            CP_ASYNC16(st + so,         g_rel_f16 + (rbase + row) * 512 + kcol + u * 8);
            CP_ASYNC16(st + 16384 + so, Bp + (size_t)row * 512 + kcol + u * 8);
        }
        CP_COMMIT();
    };

    issue_full(0); issue_full(1);

    for (int kc = 0; kc < 64; kc++) {
        const bool pf = (kc + 2 < 64);
        if (pf) { CP_WAIT1(); } else { CP_WAIT0(); }
        __syncthreads();

        const int kp = kc + 2;
        const uint32_t stP = sb + (kp % 3) * KSTG;
        const __half* ApP = g_rel_f16 + rbase * 512 + ((kp & 7) * 64);
        const __half* BpP = g_w_f16 + (size_t)(kp >> 3) * 128 * 512 + ((kp & 7) * 64);

        const uint32_t stA = sb + (kc % 3) * KSTG;
        const uint32_t stB = stA + 16384;
        const int r8 = lane & 7, sel = lane >> 3;
#pragma unroll
        for (int ks = 0; ks < 4; ks++) {
            if (pf) {
                int idx = tid + ks * 256;
                int row = idx >> 3, u = idx & 7;
                uint32_t so = SMEM_SWZ(row * 128 + u * 16);
                CP_ASYNC16(stP + so,         ApP + (size_t)row * 512 + u * 8);
                CP_ASYNC16(stP + 16384 + so, BpP + (size_t)row * 512 + u * 8);
            }
            uint32_t a[2][4];
#pragma unroll
            for (int mt = 0; mt < 2; mt++) {
                int row = wm * 32 + mt * 16 + r8 + (sel & 1) * 8;
                int c16 = ks * 2 + (sel >> 1);
                ldmx4(a[mt][0], a[mt][1], a[mt][2], a[mt][3],
                      stA + SMEM_SWZ(row * 128 + c16 * 16));
            }
            uint32_t bq[4][2], bk[4][2];
#pragma unroll
            for (int gp = 0; gp < 2; gp++) {
                int c16 = ks * 2 + (sel & 1);
                int rowq = wn * 32 + gp * 16 + r8 + (sel >> 1) * 8;
                ldmx4(bq[gp*2][0], bq[gp*2][1], bq[gp*2+1][0], bq[gp*2+1][1],
                      stB + SMEM_SWZ(rowq * 128 + c16 * 16));
                int rowk = 64 + rowq;
                ldmx4(bk[gp*2][0], bk[gp*2][1], bk[gp*2+1][0], bk[gp*2+1][1],
                      stB + SMEM_SWZ(rowk * 128 + c16 * 16));
            }
#pragma unroll
            for (int mt = 0; mt < 2; mt++)
#pragma unroll
                for (int g = 0; g < 4; g++) {
                    mma_f16(c[mt][g],   a[mt], bq[g][0], bq[g][1]);
                    mma_f16(c[mt][4+g], a[mt], bk[g][0], bk[g][1]);
                }
        }
        if (pf) CP_COMMIT();

        if ((kc & 7) == 7) {
            const int h = kc >> 3;
            float* parr = (float*)(smem + (kc % 3) * KSTG);
#pragma unroll
            for (int mt = 0; mt < 2; mt++)
#pragma unroll
                for (int rh = 0; rh < 2; rh++) {
                    const int R = wm * 32 + mt * 16 + (lane >> 2) + rh * 8;
                    int gi = t * 128 + R;
                    const int e = lst[gi < cnt ? gi : cnt - 1];
                    const float* qrow = g_q + ((size_t)(b * Ll + (e & 255))) * Ee + h * 64;
                    const float* krow = g_k + ((size_t)(b * Ll + (e >> 8))) * Ee + h * 64;
                    float acc = 0.f;
#pragma unroll
                    for (int g = 0; g < 4; g++) {
                        const int d0 = wn * 32 + g * 8 + 2 * (lane & 3);
                        acc += (qrow[d0]     + c[mt][g][rh*2+0]) * (krow[d0]     + c[mt][4+g][rh*2+0]);
                        acc += (qrow[d0 + 1] + c[mt][g][rh*2+1]) * (krow[d0 + 1] + c[mt][4+g][rh*2+1]);
                    }
                    acc += __shfl_xor_sync(0xffffffffu, acc, 1);
                    acc += __shfl_xor_sync(0xffffffffu, acc, 2);
                    if ((lane & 3) == 0) parr[wn * 128 + R] = acc;
                }
            __syncthreads();
            if (tid < 128 && t * 128 + tid < cnt) {
                const int e = lst[t * 128 + tid];
                float lg = parr[tid] + parr[128 + tid];
                g_logits[((size_t)(b * Hh + h) * Ll + (e & 255)) * Ll + (e >> 8)] = lg;
            }
            __syncthreads();
#pragma unroll
            for (int mt = 0; mt < 2; mt++)
#pragma unroll
                for (int g = 0; g < 8; g++)
#pragma unroll
                    for (int e2 = 0; e2 < 4; e2++) c[mt][g][e2] = 0.f;
        }
    }
}

// ==================== fused softmax + PV ====================
#define SPV_SMEM ((64*256 + 256*64) * 4)
__global__ __launch_bounds__(256, 1)
void softpv_kernel(const int* __restrict__ adj, float* __restrict__ out_attn)
{
    extern __shared__ float sm[];
    float* Ws = sm;
    float* Vs = sm + 64 * 256;
    int it = blockIdx.x, h = blockIdx.y, b = blockIdx.z;
    int i0 = it * 64;
    int tid = threadIdx.x, lane = tid & 31, w = tid >> 5;

    size_t lb = (((size_t)b * Hh + h) * Ll + i0) * Ll;
    const float4* lsrc = (const float4*)(g_logits + lb);
    float4* wdst = (float4*)Ws;
    for (int idx = tid; idx < 64 * 256 / 4; idx += 256) wdst[idx] = lsrc[idx];
    float4* vdst = (float4*)Vs;
    for (int idx = tid; idx < 256 * 64 / 4; idx += 256) {
        int jrow = idx >> 4, d4 = idx & 15;
        vdst[idx] = *(const float4*)(g_v + ((size_t)b * Ll + jrow) * Ee + h * 64 + d4 * 4);
    }
    __syncthreads();

    for (int r = w * 8; r < w * 8 + 8; r++) {
        int i = i0 + r;
        const int* arow = adj + ((size_t)(b * Ll + i)) * Ll;
        float v[8]; bool msk[8];
        float mx = -CUDART_INF_F;
#pragma unroll
        for (int u = 0; u < 8; u++) {
            int j = lane + u * 32;
            msk[u] = (arow[j] == 1);
            v[u] = msk[u] ? -CUDART_INF_F : Ws[r * 256 + j];
            mx = fmaxf(mx, v[u]);
        }
#pragma unroll
        for (int o = 16; o > 0; o >>= 1) mx = fmaxf(mx, __shfl_xor_sync(0xffffffffu, mx, o));
        float s = 0.f;
#pragma unroll
        for (int u = 0; u < 8; u++) {
            v[u] = msk[u] ? 0.f : expf(v[u] - mx);
            s += v[u];
        }
#pragma unroll
        for (int o = 16; o > 0; o >>= 1) s += __shfl_xor_sync(0xffffffffu, s, o);
        float inv = 1.0f / s;
#pragma unroll
        for (int u = 0; u < 8; u++) {
            int j = lane + u * 32;
            float wgt = v[u] * inv;
            Ws[r * 256 + j] = wgt;
            out_attn[(((size_t)b * Ll + i) * Ll + j) * Hh + h] = wgt;
        }
    }
    __syncthreads();

    int i = tid >> 2, tq = tid & 3;
    float acc[16];
#pragma unroll
    for (int dd = 0; dd < 16; dd++) acc[dd] = 0.f;
    const float* wrow = Ws + i * 256;
    for (int jj = 0; jj < 256; jj += 4) {
        float4 wv = *(const float4*)(wrow + jj);
#pragma unroll
        for (int u = 0; u < 4; u++) {
            float wsc = (u == 0) ? wv.x : (u == 1) ? wv.y : (u == 2) ? wv.z : wv.w;
            const float* vr = Vs + (jj + u) * 64 + tq * 16;
#pragma unroll
            for (int dd = 0; dd < 16; dd++) acc[dd] += wsc * vr[dd];
        }
    }
    float* op = g_o1 + ((size_t)b * Ll + i0 + i) * Ee + h * 64 + tq * 16;
#pragma unroll
    for (int dd = 0; dd < 16; dd++) op[dd] = acc[dd];
}

// ==================== output GEMM (double-buffered) ====================
__global__ __launch_bounds__(256)
void gemm_bias_kernel(const float* __restrict__ X, const float* __restrict__ W,
                      const float* __restrict__ bias, float* __restrict__ Y,
                      int Mdim, int Ndim, int Kdim, float scale)
{
    __shared__ float Xs[16][64];
    __shared__ float Ws[16][64];
    gemm64_db(X, W, bias, Y, blockIdx.y * 64, blockIdx.x * 64, Kdim, Ndim, scale, Xs, Ws);
}

// ---------------------------------------------------------------------------
extern "C" void kernel_launch(void* const* d_in, const int* in_sizes, int n_in,
                              void* d_out, int out_size)
{
    (void)in_sizes; (void)n_in; (void)out_size;
    const float* queries  = (const float*)d_in[0];
    const float* keys     = (const float*)d_in[1];
    const float* values   = (const float*)d_in[2];
    const float* relation = (const float*)d_in[3];
    const int*   adj      = (const int*)d_in[4];
    const float* Wq = (const float*)d_in[5];
    const float* bq = (const float*)d_in[6];
    const float* Wk = (const float*)d_in[7];
    const float* bk = (const float*)d_in[8];
    const float* Wv = (const float*)d_in[9];
    const float* bv = (const float*)d_in[10];
    const float* Wr = (const float*)d_in[11];
    const float* Wo = (const float*)d_in[12];
    const float* bo = (const float*)d_in[13];

    float* out      = (float*)d_out;
    float* out_attn = out + Bb * Ll * Ee;

    float *o1p;
    cudaGetSymbolAddress((void**)&o1p, g_o1);

    cudaFuncSetAttribute(rel_attn_mma_kernel, cudaFuncAttributeMaxDynamicSharedMemorySize, MMA_SMEM);
    cudaFuncSetAttribute(softpv_kernel, cudaFuncAttributeMaxDynamicSharedMemorySize, SPV_SMEM);

    split_w_kernel<<<1024, 128>>>(Wr);
    compact_qkv_kernel<<<704, 256>>>(adj, queries, keys, values,
                                     Wq, bq, Wk, bk, Wv, bv);
    split_rel_gather_kernel<<<dim3(Ll*Ll/2, Bb), 256>>>(relation);
    rel_attn_mma_kernel<<<dim3(512, Bb), 256, MMA_SMEM>>>();
    softpv_kernel<<<dim3(Ll / 64, Hh, Bb), 256, SPV_SMEM>>>(adj, out_attn);
    gemm_bias_kernel<<<dim3(Ee/64, (Bb*Ll)/64), 256>>>(o1p, Wo, bo, out, Bb*Ll, Ee, Ee, 1.0f);
}

// round 15
// speedup vs baseline: 1.0068x; 1.0068x over previous
#include <cuda_runtime.h>
#include <cuda_fp16.h>
#include <cstdint>
#include <math_constants.h>

#define Bb 2
#define Ll 256
#define Ee 512
#define Hh 8
#define QSCALE 0.125f

// ---------------- device scratch ----------------
__device__ float g_q[Bb*Ll*Ee];
__device__ float g_k[Bb*Ll*Ee];
__device__ float g_v[Bb*Ll*Ee];
__device__ float g_logits[(size_t)Bb*Hh*Ll*Ll];
__device__ float g_o1[Bb*Ll*Ee];
// fp16 (rne) copies; relation rows compacted in list order
__device__ __half g_rel_f16[(size_t)Bb*Ll*Ll*Ee];
__device__ __half g_w_f16[1024*512];   // [h*128+p][k]; p<64: Wrq rows, p>=64: Wrk rows
__device__ int g_cnt[Bb];
__device__ unsigned short g_list[Bb*Ll*Ll];

// ==================== PTX helpers ====================
__device__ __forceinline__ uint32_t smem_u32(const void* p) {
    uint32_t a;
    asm("{ .reg .u64 t; cvta.to.shared.u64 t, %1; cvt.u32.u64 %0, t; }" : "=r"(a) : "l"(p));
    return a;
}
#define SMEM_SWZ(o) ((o) ^ (((o) >> 3) & 0x70))
#define CP_ASYNC16(dst, src) \
    asm volatile("cp.async.cg.shared.global [%0], [%1], 16;" :: "r"(dst), "l"(src))
#define CP_COMMIT() asm volatile("cp.async.commit_group;" ::: "memory")
#define CP_WAIT1() asm volatile("cp.async.wait_group 1;" ::: "memory")
#define CP_WAIT0() asm volatile("cp.async.wait_group 0;" ::: "memory")

__device__ __forceinline__ void ldmx4(uint32_t& r0, uint32_t& r1, uint32_t& r2, uint32_t& r3, uint32_t addr) {
    asm volatile("ldmatrix.sync.aligned.m8n8.x4.shared.b16 {%0,%1,%2,%3}, [%4];"
        : "=r"(r0), "=r"(r1), "=r"(r2), "=r"(r3) : "r"(addr));
}
// m16n8k16 fp16 MMA, fp32 accumulate
__device__ __forceinline__ void mma_f16(float* c, const uint32_t* a, uint32_t b0, uint32_t b1) {
    asm volatile("mma.sync.aligned.m16n8k16.row.col.f32.f16.f16.f32 "
        "{%0,%1,%2,%3}, {%4,%5,%6,%7}, {%8,%9}, {%0,%1,%2,%3};"
        : "+f"(c[0]), "+f"(c[1]), "+f"(c[2]), "+f"(c[3])
        : "r"(a[0]), "r"(a[1]), "r"(a[2]), "r"(a[3]), "r"(b0), "r"(b1));
}

__device__ __forceinline__ void cvt4_f16(float4 v, __half* dst) {
    __half2* d2 = (__half2*)dst;
    d2[0] = __floats2half2_rn(v.x, v.y);
    d2[1] = __floats2half2_rn(v.z, v.w);
}

// ==================== double-buffered fp32 GEMM body ====================
__device__ __forceinline__ void gemm64_db(const float* __restrict__ X,
                                          const float* __restrict__ W,
                                          const float* __restrict__ bias,
                                          float* __restrict__ Y,
                                          int m0, int n0, int Kdim, int Ndim,
                                          float scale,
                                          float Xs[16][64], float Ws[16][64])
{
    int tid = threadIdx.x;
    int ty = tid >> 4, tx = tid & 15;
    int r = tid >> 2, c4 = tid & 3;
    float acc[4][4];
#pragma unroll
    for (int a = 0; a < 4; a++)
#pragma unroll
        for (int bb = 0; bb < 4; bb++) acc[a][bb] = 0.f;

    float4 xv = *(const float4*)(X + (size_t)(m0 + r) * Kdim + c4 * 4);
    float4 wv = *(const float4*)(W + (size_t)(n0 + r) * Kdim + c4 * 4);
    for (int kc = 0; kc < Kdim; kc += 16) {
        __syncthreads();
        Xs[c4*4+0][r]=xv.x; Xs[c4*4+1][r]=xv.y; Xs[c4*4+2][r]=xv.z; Xs[c4*4+3][r]=xv.w;
        Ws[c4*4+0][r]=wv.x; Ws[c4*4+1][r]=wv.y; Ws[c4*4+2][r]=wv.z; Ws[c4*4+3][r]=wv.w;
        __syncthreads();
        if (kc + 16 < Kdim) {
            xv = *(const float4*)(X + (size_t)(m0 + r) * Kdim + kc + 16 + c4 * 4);
            wv = *(const float4*)(W + (size_t)(n0 + r) * Kdim + kc + 16 + c4 * 4);
        }
#pragma unroll
        for (int cc = 0; cc < 16; cc++) {
            float4 a = *(const float4*)&Xs[cc][ty*4];
            float4 bv4 = *(const float4*)&Ws[cc][tx*4];
            acc[0][0]+=a.x*bv4.x; acc[0][1]+=a.x*bv4.y; acc[0][2]+=a.x*bv4.z; acc[0][3]+=a.x*bv4.w;
            acc[1][0]+=a.y*bv4.x; acc[1][1]+=a.y*bv4.y; acc[1][2]+=a.y*bv4.z; acc[1][3]+=a.y*bv4.w;
            acc[2][0]+=a.z*bv4.x; acc[2][1]+=a.z*bv4.y; acc[2][2]+=a.z*bv4.z; acc[2][3]+=a.z*bv4.w;
            acc[3][0]+=a.w*bv4.x; acc[3][1]+=a.w*bv4.y; acc[3][2]+=a.w*bv4.z; acc[3][3]+=a.w*bv4.w;
        }
    }
#pragma unroll
    for (int rr = 0; rr < 4; rr++)
#pragma unroll
        for (int cc = 0; cc < 4; cc++)
            Y[(size_t)(m0+ty*4+rr) * Ndim + n0+tx*4+cc] = (acc[rr][cc] + bias[n0+tx*4+cc]) * scale;
}

// ==================== merged pre-pass: W-split | compaction | qkv ====================
// blocks 0..511   : Wr fp16 split (2 rows/block)
// blocks 512..1023: mask compaction (block = (j,b))          [g_cnt pre-zeroed via memset]
// blocks 1024..1215: q/k/v projection GEMM tiles
__global__ __launch_bounds__(256)
void pre_kernel(const float* __restrict__ Wr, const int* __restrict__ adj,
                const float* __restrict__ queries, const float* __restrict__ keys,
                const float* __restrict__ values,
                const float* __restrict__ Wq, const float* __restrict__ bq,
                const float* __restrict__ Wk, const float* __restrict__ bk,
                const float* __restrict__ Wv, const float* __restrict__ bv)
{
    const int bid = blockIdx.x;
    const int tid = threadIdx.x;
    if (bid < 512) {
        // ---- Wr split: rows r = bid*2 + (tid>>7) ----
        int r = bid * 2 + (tid >> 7);
        int h = r >> 7, p = r & 127;
        int in_row = (p < 64) ? (h*64 + p) : (512 + h*64 + (p - 64));
        int t = tid & 127;
        float4 v = ((const float4*)(Wr + (size_t)in_row * 512))[t];
        cvt4_f16(v, g_w_f16 + (size_t)r * 512 + t * 4);
        return;
    }
    if (bid < 1024) {
        // ---- compaction ----
        int j = (bid - 512) & 255, b = (bid - 512) >> 8, i = tid;
        int lane = i & 31, w = i >> 5;
        bool keep = adj[((size_t)(b * Ll + i)) * Ll + j] != 1;
        unsigned m = __ballot_sync(0xffffffffu, keep);
        int wpos = __popc(m & ((1u << lane) - 1));
        __shared__ int wcnt[8], wbase[9];
        if (lane == 0) wcnt[w] = __popc(m);
        __syncthreads();
        if (i == 0) {
            int s = 0;
            for (int x = 0; x < 8; x++) { wbase[x] = s; s += wcnt[x]; }
            wbase[8] = atomicAdd(&g_cnt[b], s);
        }
        __syncthreads();
        if (keep) g_list[b * (Ll*Ll) + wbase[8] + wbase[w] + wpos] = (unsigned short)((j << 8) | i);
        return;
    }
    // ---- qkv GEMMs ----
    int bid2 = bid - 1024;
    int z = bid2 >> 6, rem = bid2 & 63;
    const float* X = (z == 0) ? queries : (z == 1) ? keys : values;
    const float* W = (z == 0) ? Wq : (z == 1) ? Wk : Wv;
    const float* bias = (z == 0) ? bq : (z == 1) ? bk : bv;
    float* Y = (z == 0) ? g_q : (z == 1) ? g_k : g_v;
    const float scale = (z == 0) ? QSCALE : 1.0f;

    __shared__ float Xs[16][64];
    __shared__ float Ws[16][64];
    gemm64_db(X, W, bias, Y, (rem >> 3) * 64, (rem & 7) * 64, Ee, Ee, scale, Xs, Ws);
}

// Gather + fp16-round ONLY unmasked rel rows; grid-stride (no launch tail).
__global__ __launch_bounds__(256)
void split_rel_gather_kernel(const float* __restrict__ rel) {
    int b = blockIdx.y;
    const int cnt = g_cnt[b];
    int t = threadIdx.x & 127;
    for (int ent = blockIdx.x * 2 + (threadIdx.x >> 7); ent < cnt; ent += gridDim.x * 2) {
        int e = g_list[b * (Ll*Ll) + ent];
        float4 v = ((const float4*)(rel + ((size_t)(b * (Ll*Ll)) + e) * 512))[t];
        cvt4_f16(v, g_rel_f16 + ((size_t)(b * (Ll*Ll)) + ent) * 512 + t * 4);
    }
}

// ==================== fp16 mma.sync relation attention ====================
// CTA = tile of 128 compacted pairs, 256 threads, occ 2.
// 64 kc-chunks of 64 halves (8 per head). Stage = A 16KB + B 16KB = 32KB;
// 3-deep ring (96KB), prefetch distance 2, cp.async interleaved into ks loop.
#define KSTG 32768
#define MMA_SMEM (3*KSTG)        // 98304

__global__ void __launch_bounds__(256, 2) rel_attn_mma_kernel()
{
    extern __shared__ char smem[];
    const uint32_t sb = smem_u32(smem);
    const int tid = threadIdx.x, lane = tid & 31, w = tid >> 5;
    const int wm = w & 3, wn = w >> 2;
    const int t = blockIdx.x, b = blockIdx.y;

    const int cnt = g_cnt[b];
    if (t * 128 >= cnt) return;
    const size_t rbase = (size_t)(b * (Ll*Ll)) + t * 128;
    const unsigned short* lst = g_list + b * (Ll*Ll);

    float c[2][8][4];
#pragma unroll
    for (int mt = 0; mt < 2; mt++)
#pragma unroll
        for (int g = 0; g < 8; g++)
#pragma unroll
            for (int e = 0; e < 4; e++) c[mt][g][e] = 0.f;

    auto issue_full = [&](int kc) {
        const int h = kc >> 3;
        const int kcol = (kc & 7) * 64;
        const uint32_t st = sb + (kc % 3) * KSTG;
        const __half* Bp = g_w_f16 + (size_t)h * 128 * 512;
#pragma unroll
        for (int r4 = 0; r4 < 4; r4++) {
            int idx = tid + r4 * 256;
            int row = idx >> 3, u = idx & 7;
            uint32_t so = SMEM_SWZ(row * 128 + u * 16);
            CP_ASYNC16(st + so,         g_rel_f16 + (rbase + row) * 512 + kcol + u * 8);
            CP_ASYNC16(st + 16384 + so, Bp + (size_t)row * 512 + kcol + u * 8);
        }
        CP_COMMIT();
    };

    issue_full(0); issue_full(1);

    for (int kc = 0; kc < 64; kc++) {
        const bool pf = (kc + 2 < 64);
        if (pf) { CP_WAIT1(); } else { CP_WAIT0(); }
        __syncthreads();

        const int kp = kc + 2;
        const uint32_t stP = sb + (kp % 3) * KSTG;
        const __half* ApP = g_rel_f16 + rbase * 512 + ((kp & 7) * 64);
        const __half* BpP = g_w_f16 + (size_t)(kp >> 3) * 128 * 512 + ((kp & 7) * 64);

        const uint32_t stA = sb + (kc % 3) * KSTG;
        const uint32_t stB = stA + 16384;
        const int r8 = lane & 7, sel = lane >> 3;
#pragma unroll
        for (int ks = 0; ks < 4; ks++) {
            if (pf) {
                int idx = tid + ks * 256;
                int row = idx >> 3, u = idx & 7;
                uint32_t so = SMEM_SWZ(row * 128 + u * 16);
                CP_ASYNC16(stP + so,         ApP + (size_t)row * 512 + u * 8);
                CP_ASYNC16(stP + 16384 + so, BpP + (size_t)row * 512 + u * 8);
            }
            uint32_t a[2][4];
#pragma unroll
            for (int mt = 0; mt < 2; mt++) {
                int row = wm * 32 + mt * 16 + r8 + (sel & 1) * 8;
                int c16 = ks * 2 + (sel >> 1);
                ldmx4(a[mt][0], a[mt][1], a[mt][2], a[mt][3],
                      stA + SMEM_SWZ(row * 128 + c16 * 16));
            }
            uint32_t bq[4][2], bk[4][2];
#pragma unroll
            for (int gp = 0; gp < 2; gp++) {
                int c16 = ks * 2 + (sel & 1);
                int rowq = wn * 32 + gp * 16 + r8 + (sel >> 1) * 8;
                ldmx4(bq[gp*2][0], bq[gp*2][1], bq[gp*2+1][0], bq[gp*2+1][1],
                      stB + SMEM_SWZ(rowq * 128 + c16 * 16));
                int rowk = 64 + rowq;
                ldmx4(bk[gp*2][0], bk[gp*2][1], bk[gp*2+1][0], bk[gp*2+1][1],
                      stB + SMEM_SWZ(rowk * 128 + c16 * 16));
            }
#pragma unroll
            for (int mt = 0; mt < 2; mt++)
#pragma unroll
                for (int g = 0; g < 4; g++) {
                    mma_f16(c[mt][g],   a[mt], bq[g][0], bq[g][1]);
                    mma_f16(c[mt][4+g], a[mt], bk[g][0], bk[g][1]);
                }
        }
        if (pf) CP_COMMIT();

        if ((kc & 7) == 7) {
            const int h = kc >> 3;
            float* parr = (float*)(smem + (kc % 3) * KSTG);
#pragma unroll
            for (int mt = 0; mt < 2; mt++)
#pragma unroll
                for (int rh = 0; rh < 2; rh++) {
                    const int R = wm * 32 + mt * 16 + (lane >> 2) + rh * 8;
                    int gi = t * 128 + R;
                    const int e = lst[gi < cnt ? gi : cnt - 1];
                    const float* qrow = g_q + ((size_t)(b * Ll + (e & 255))) * Ee + h * 64;
                    const float* krow = g_k + ((size_t)(b * Ll + (e >> 8))) * Ee + h * 64;
                    float acc = 0.f;
#pragma unroll
                    for (int g = 0; g < 4; g++) {
                        const int d0 = wn * 32 + g * 8 + 2 * (lane & 3);
                        acc += (qrow[d0]     + c[mt][g][rh*2+0]) * (krow[d0]     + c[mt][4+g][rh*2+0]);
                        acc += (qrow[d0 + 1] + c[mt][g][rh*2+1]) * (krow[d0 + 1] + c[mt][4+g][rh*2+1]);
                    }
                    acc += __shfl_xor_sync(0xffffffffu, acc, 1);
                    acc += __shfl_xor_sync(0xffffffffu, acc, 2);
                    if ((lane & 3) == 0) parr[wn * 128 + R] = acc;
                }
            __syncthreads();
            if (tid < 128 && t * 128 + tid < cnt) {
                const int e = lst[t * 128 + tid];
                float lg = parr[tid] + parr[128 + tid];
                g_logits[((size_t)(b * Hh + h) * Ll + (e & 255)) * Ll + (e >> 8)] = lg;
            }
            __syncthreads();
#pragma unroll
            for (int mt = 0; mt < 2; mt++)
#pragma unroll
                for (int g = 0; g < 8; g++)
#pragma unroll
                    for (int e2 = 0; e2 < 4; e2++) c[mt][g][e2] = 0.f;
        }
    }
}

// ==================== fused softmax + PV ====================
#define SPV_SMEM ((64*256 + 256*64) * 4)
__global__ __launch_bounds__(256, 1)
void softpv_kernel(const int* __restrict__ adj, float* __restrict__ out_attn)
{
    extern __shared__ float sm[];
    float* Ws = sm;
    float* Vs = sm + 64 * 256;
    int it = blockIdx.x, h = blockIdx.y, b = blockIdx.z;
    int i0 = it * 64;
    int tid = threadIdx.x, lane = tid & 31, w = tid >> 5;

    size_t lb = (((size_t)b * Hh + h) * Ll + i0) * Ll;
    const float4* lsrc = (const float4*)(g_logits + lb);
    float4* wdst = (float4*)Ws;
    for (int idx = tid; idx < 64 * 256 / 4; idx += 256) wdst[idx] = lsrc[idx];
    float4* vdst = (float4*)Vs;
    for (int idx = tid; idx < 256 * 64 / 4; idx += 256) {
        int jrow = idx >> 4, d4 = idx & 15;
        vdst[idx] = *(const float4*)(g_v + ((size_t)b * Ll + jrow) * Ee + h * 64 + d4 * 4);
    }
    __syncthreads();

    for (int r = w * 8; r < w * 8 + 8; r++) {
        int i = i0 + r;
        const int* arow = adj + ((size_t)(b * Ll + i)) * Ll;
        float v[8]; bool msk[8];
        float mx = -CUDART_INF_F;
#pragma unroll
        for (int u = 0; u < 8; u++) {
            int j = lane + u * 32;
            msk[u] = (arow[j] == 1);
            v[u] = msk[u] ? -CUDART_INF_F : Ws[r * 256 + j];
            mx = fmaxf(mx, v[u]);
        }
#pragma unroll
        for (int o = 16; o > 0; o >>= 1) mx = fmaxf(mx, __shfl_xor_sync(0xffffffffu, mx, o));
        float s = 0.f;
#pragma unroll
        for (int u = 0; u < 8; u++) {
            v[u] = msk[u] ? 0.f : expf(v[u] - mx);
            s += v[u];
        }
#pragma unroll
        for (int o = 16; o > 0; o >>= 1) s += __shfl_xor_sync(0xffffffffu, s, o);
        float inv = 1.0f / s;
#pragma unroll
        for (int u = 0; u < 8; u++) {
            int j = lane + u * 32;
            float wgt = v[u] * inv;
            Ws[r * 256 + j] = wgt;
            out_attn[(((size_t)b * Ll + i) * Ll + j) * Hh + h] = wgt;
        }
    }
    __syncthreads();

    int i = tid >> 2, tq = tid & 3;
    float acc[16];
#pragma unroll
    for (int dd = 0; dd < 16; dd++) acc[dd] = 0.f;
    const float* wrow = Ws + i * 256;
    for (int jj = 0; jj < 256; jj += 4) {
        float4 wv = *(const float4*)(wrow + jj);
#pragma unroll
        for (int u = 0; u < 4; u++) {
            float wsc = (u == 0) ? wv.x : (u == 1) ? wv.y : (u == 2) ? wv.z : wv.w;
            const float* vr = Vs + (jj + u) * 64 + tq * 16;
#pragma unroll
            for (int dd = 0; dd < 16; dd++) acc[dd] += wsc * vr[dd];
        }
    }
    float* op = g_o1 + ((size_t)b * Ll + i0 + i) * Ee + h * 64 + tq * 16;
#pragma unroll
    for (int dd = 0; dd < 16; dd++) op[dd] = acc[dd];
}

// ==================== output GEMM ====================
__global__ __launch_bounds__(256)
void gemm_bias_kernel(const float* __restrict__ X, const float* __restrict__ W,
                      const float* __restrict__ bias, float* __restrict__ Y,
                      int Mdim, int Ndim, int Kdim, float scale)
{
    __shared__ float Xs[16][64];
    __shared__ float Ws[16][64];
    gemm64_db(X, W, bias, Y, blockIdx.y * 64, blockIdx.x * 64, Kdim, Ndim, scale, Xs, Ws);
}

// ---------------------------------------------------------------------------
extern "C" void kernel_launch(void* const* d_in, const int* in_sizes, int n_in,
                              void* d_out, int out_size)
{
    (void)in_sizes; (void)n_in; (void)out_size;
    const float* queries  = (const float*)d_in[0];
    const float* keys     = (const float*)d_in[1];
    const float* values   = (const float*)d_in[2];
    const float* relation = (const float*)d_in[3];
    const int*   adj      = (const int*)d_in[4];
    const float* Wq = (const float*)d_in[5];
    const float* bq = (const float*)d_in[6];
    const float* Wk = (const float*)d_in[7];
    const float* bk = (const float*)d_in[8];
    const float* Wv = (const float*)d_in[9];
    const float* bv = (const float*)d_in[10];
    const float* Wr = (const float*)d_in[11];
    const float* Wo = (const float*)d_in[12];
    const float* bo = (const float*)d_in[13];

    float* out      = (float*)d_out;
    float* out_attn = out + Bb * Ll * Ee;

    float *o1p; int *cntp;
    cudaGetSymbolAddress((void**)&o1p, g_o1);
    cudaGetSymbolAddress((void**)&cntp, g_cnt);

    cudaFuncSetAttribute(rel_attn_mma_kernel, cudaFuncAttributeMaxDynamicSharedMemorySize, MMA_SMEM);
    cudaFuncSetAttribute(softpv_kernel, cudaFuncAttributeMaxDynamicSharedMemorySize, SPV_SMEM);

    cudaMemsetAsync(cntp, 0, Bb * sizeof(int));
    pre_kernel<<<1216, 256>>>(Wr, adj, queries, keys, values,
                              Wq, bq, Wk, bk, Wv, bv);
    split_rel_gather_kernel<<<dim3(2048, Bb), 256>>>(relation);
    rel_attn_mma_kernel<<<dim3(512, Bb), 256, MMA_SMEM>>>();
    softpv_kernel<<<dim3(Ll / 64, Hh, Bb), 256, SPV_SMEM>>>(adj, out_attn);
    gemm_bias_kernel<<<dim3(Ee/64, (Bb*Ll)/64), 256>>>(o1p, Wo, bo, out, Bb*Ll, Ee, Ee, 1.0f);
}

// round 16
// speedup vs baseline: 1.0747x; 1.0675x over previous
#include <cuda_runtime.h>
#include <cuda_fp16.h>
#include <cstdint>
#include <math_constants.h>

#define Bb 2
#define Ll 256
#define Ee 512
#define Hh 8
#define QSCALE 0.125f

// ---------------- device scratch ----------------
__device__ float g_q[Bb*Ll*Ee];
__device__ float g_k[Bb*Ll*Ee];
__device__ float g_v[Bb*Ll*Ee];
__device__ float g_logits[(size_t)Bb*Hh*Ll*Ll];
__device__ float g_o1[Bb*Ll*Ee];
__device__ __half g_rel_f16[(size_t)Bb*Ll*Ll*Ee];
__device__ __half g_w_f16[1024*512];   // [h*128+p][k]; p<64: Wrq rows, p>=64: Wrk rows
__device__ int g_cnt[Bb];
__device__ unsigned short g_list[Bb*Ll*Ll];

// ==================== PTX helpers ====================
__device__ __forceinline__ uint32_t smem_u32(const void* p) {
    uint32_t a;
    asm("{ .reg .u64 t; cvta.to.shared.u64 t, %1; cvt.u32.u64 %0, t; }" : "=r"(a) : "l"(p));
    return a;
}
#define SMEM_SWZ(o) ((o) ^ (((o) >> 3) & 0x70))
#define CP_ASYNC16(dst, src) \
    asm volatile("cp.async.cg.shared.global [%0], [%1], 16;" :: "r"(dst), "l"(src))
#define CP_COMMIT() asm volatile("cp.async.commit_group;" ::: "memory")
#define CP_WAIT1() asm volatile("cp.async.wait_group 1;" ::: "memory")
#define CP_WAIT0() asm volatile("cp.async.wait_group 0;" ::: "memory")

__device__ __forceinline__ void ldmx4(uint32_t& r0, uint32_t& r1, uint32_t& r2, uint32_t& r3, uint32_t addr) {
    asm volatile("ldmatrix.sync.aligned.m8n8.x4.shared.b16 {%0,%1,%2,%3}, [%4];"
        : "=r"(r0), "=r"(r1), "=r"(r2), "=r"(r3) : "r"(addr));
}
__device__ __forceinline__ void mma_f16(float* c, const uint32_t* a, uint32_t b0, uint32_t b1) {
    asm volatile("mma.sync.aligned.m16n8k16.row.col.f32.f16.f16.f32 "
        "{%0,%1,%2,%3}, {%4,%5,%6,%7}, {%8,%9}, {%0,%1,%2,%3};"
        : "+f"(c[0]), "+f"(c[1]), "+f"(c[2]), "+f"(c[3])
        : "r"(a[0]), "r"(a[1]), "r"(a[2]), "r"(a[3]), "r"(b0), "r"(b1));
}
__device__ __forceinline__ void cvt4_f16(float4 v, __half* dst) {
    __half2* d2 = (__half2*)dst;
    d2[0] = __floats2half2_rn(v.x, v.y);
    d2[1] = __floats2half2_rn(v.z, v.w);
}

// ==================== double-buffered fp32 GEMM bodies ====================
// 64x64 tile (used by qkv inside pre_kernel)
__device__ __forceinline__ void gemm64_db(const float* __restrict__ X,
                                          const float* __restrict__ W,
                                          const float* __restrict__ bias,
                                          float* __restrict__ Y,
                                          int m0, int n0, int Kdim, int Ndim,
                                          float scale,
                                          float Xs[16][64], float Ws[16][64])
{
    int tid = threadIdx.x;
    int ty = tid >> 4, tx = tid & 15;
    int r = tid >> 2, c4 = tid & 3;
    float acc[4][4];
#pragma unroll
    for (int a = 0; a < 4; a++)
#pragma unroll
        for (int bb = 0; bb < 4; bb++) acc[a][bb] = 0.f;

    float4 xv = *(const float4*)(X + (size_t)(m0 + r) * Kdim + c4 * 4);
    float4 wv = *(const float4*)(W + (size_t)(n0 + r) * Kdim + c4 * 4);
    for (int kc = 0; kc < Kdim; kc += 16) {
        __syncthreads();
        Xs[c4*4+0][r]=xv.x; Xs[c4*4+1][r]=xv.y; Xs[c4*4+2][r]=xv.z; Xs[c4*4+3][r]=xv.w;
        Ws[c4*4+0][r]=wv.x; Ws[c4*4+1][r]=wv.y; Ws[c4*4+2][r]=wv.z; Ws[c4*4+3][r]=wv.w;
        __syncthreads();
        if (kc + 16 < Kdim) {
            xv = *(const float4*)(X + (size_t)(m0 + r) * Kdim + kc + 16 + c4 * 4);
            wv = *(const float4*)(W + (size_t)(n0 + r) * Kdim + kc + 16 + c4 * 4);
        }
#pragma unroll
        for (int cc = 0; cc < 16; cc++) {
            float4 a = *(const float4*)&Xs[cc][ty*4];
            float4 bv4 = *(const float4*)&Ws[cc][tx*4];
            acc[0][0]+=a.x*bv4.x; acc[0][1]+=a.x*bv4.y; acc[0][2]+=a.x*bv4.z; acc[0][3]+=a.x*bv4.w;
            acc[1][0]+=a.y*bv4.x; acc[1][1]+=a.y*bv4.y; acc[1][2]+=a.y*bv4.z; acc[1][3]+=a.y*bv4.w;
            acc[2][0]+=a.z*bv4.x; acc[2][1]+=a.z*bv4.y; acc[2][2]+=a.z*bv4.z; acc[2][3]+=a.z*bv4.w;
            acc[3][0]+=a.w*bv4.x; acc[3][1]+=a.w*bv4.y; acc[3][2]+=a.w*bv4.z; acc[3][3]+=a.w*bv4.w;
        }
    }
#pragma unroll
    for (int rr = 0; rr < 4; rr++)
#pragma unroll
        for (int cc = 0; cc < 4; cc++)
            Y[(size_t)(m0+ty*4+rr) * Ndim + n0+tx*4+cc] = (acc[rr][cc] + bias[n0+tx*4+cc]) * scale;
}

// ==================== merged pre-pass: W-split | compaction | qkv ====================
__global__ __launch_bounds__(256)
void pre_kernel(const float* __restrict__ Wr, const int* __restrict__ adj,
                const float* __restrict__ queries, const float* __restrict__ keys,
                const float* __restrict__ values,
                const float* __restrict__ Wq, const float* __restrict__ bq,
                const float* __restrict__ Wk, const float* __restrict__ bk,
                const float* __restrict__ Wv, const float* __restrict__ bv)
{
    const int bid = blockIdx.x;
    const int tid = threadIdx.x;
    if (bid < 512) {
        int r = bid * 2 + (tid >> 7);
        int h = r >> 7, p = r & 127;
        int in_row = (p < 64) ? (h*64 + p) : (512 + h*64 + (p - 64));
        int t = tid & 127;
        float4 v = ((const float4*)(Wr + (size_t)in_row * 512))[t];
        cvt4_f16(v, g_w_f16 + (size_t)r * 512 + t * 4);
        return;
    }
    if (bid < 1024) {
        int j = (bid - 512) & 255, b = (bid - 512) >> 8, i = tid;
        int lane = i & 31, w = i >> 5;
        bool keep = adj[((size_t)(b * Ll + i)) * Ll + j] != 1;
        unsigned m = __ballot_sync(0xffffffffu, keep);
        int wpos = __popc(m & ((1u << lane) - 1));
        __shared__ int wcnt[8], wbase[9];
        if (lane == 0) wcnt[w] = __popc(m);
        __syncthreads();
        if (i == 0) {
            int s = 0;
            for (int x = 0; x < 8; x++) { wbase[x] = s; s += wcnt[x]; }
            wbase[8] = atomicAdd(&g_cnt[b], s);
        }
        __syncthreads();
        if (keep) g_list[b * (Ll*Ll) + wbase[8] + wbase[w] + wpos] = (unsigned short)((j << 8) | i);
        return;
    }
    int bid2 = bid - 1024;
    int z = bid2 >> 6, rem = bid2 & 63;
    const float* X = (z == 0) ? queries : (z == 1) ? keys : values;
    const float* W = (z == 0) ? Wq : (z == 1) ? Wk : Wv;
    const float* bias = (z == 0) ? bq : (z == 1) ? bk : bv;
    float* Y = (z == 0) ? g_q : (z == 1) ? g_k : g_v;
    const float scale = (z == 0) ? QSCALE : 1.0f;

    __shared__ float Xs[16][64];
    __shared__ float Ws[16][64];
    gemm64_db(X, W, bias, Y, (rem >> 3) * 64, (rem & 7) * 64, Ee, Ee, scale, Xs, Ws);
}

// Gather + fp16-round ONLY unmasked rel rows; grid-stride.
__global__ __launch_bounds__(256)
void split_rel_gather_kernel(const float* __restrict__ rel) {
    int b = blockIdx.y;
    const int cnt = g_cnt[b];
    int t = threadIdx.x & 127;
    for (int ent = blockIdx.x * 2 + (threadIdx.x >> 7); ent < cnt; ent += gridDim.x * 2) {
        int e = g_list[b * (Ll*Ll) + ent];
        float4 v = ((const float4*)(rel + ((size_t)(b * (Ll*Ll)) + e) * 512))[t];
        cvt4_f16(v, g_rel_f16 + ((size_t)(b * (Ll*Ll)) + ent) * 512 + t * 4);
    }
}

// ==================== fp16 mma.sync relation attention (UNCHANGED) ====================
#define KSTG 32768
#define MMA_SMEM (3*KSTG)

__global__ void __launch_bounds__(256, 2) rel_attn_mma_kernel()
{
    extern __shared__ char smem[];
    const uint32_t sb = smem_u32(smem);
    const int tid = threadIdx.x, lane = tid & 31, w = tid >> 5;
    const int wm = w & 3, wn = w >> 2;
    const int t = blockIdx.x, b = blockIdx.y;

    const int cnt = g_cnt[b];
    if (t * 128 >= cnt) return;
    const size_t rbase = (size_t)(b * (Ll*Ll)) + t * 128;
    const unsigned short* lst = g_list + b * (Ll*Ll);

    float c[2][8][4];
#pragma unroll
    for (int mt = 0; mt < 2; mt++)
#pragma unroll
        for (int g = 0; g < 8; g++)
#pragma unroll
            for (int e = 0; e < 4; e++) c[mt][g][e] = 0.f;

    auto issue_full = [&](int kc) {
        const int h = kc >> 3;
        const int kcol = (kc & 7) * 64;
        const uint32_t st = sb + (kc % 3) * KSTG;
        const __half* Bp = g_w_f16 + (size_t)h * 128 * 512;
#pragma unroll
        for (int r4 = 0; r4 < 4; r4++) {
            int idx = tid + r4 * 256;
            int row = idx >> 3, u = idx & 7;
            uint32_t so = SMEM_SWZ(row * 128 + u * 16);
            CP_ASYNC16(st + so,         g_rel_f16 + (rbase + row) * 512 + kcol + u * 8);
            CP_ASYNC16(st + 16384 + so, Bp + (size_t)row * 512 + kcol + u * 8);
        }
        CP_COMMIT();
    };

    issue_full(0); issue_full(1);

    for (int kc = 0; kc < 64; kc++) {
        const bool pf = (kc + 2 < 64);
        if (pf) { CP_WAIT1(); } else { CP_WAIT0(); }
        __syncthreads();

        const int kp = kc + 2;
        const uint32_t stP = sb + (kp % 3) * KSTG;
        const __half* ApP = g_rel_f16 + rbase * 512 + ((kp & 7) * 64);
        const __half* BpP = g_w_f16 + (size_t)(kp >> 3) * 128 * 512 + ((kp & 7) * 64);

        const uint32_t stA = sb + (kc % 3) * KSTG;
        const uint32_t stB = stA + 16384;
        const int r8 = lane & 7, sel = lane >> 3;
#pragma unroll
        for (int ks = 0; ks < 4; ks++) {
            if (pf) {
                int idx = tid + ks * 256;
                int row = idx >> 3, u = idx & 7;
                uint32_t so = SMEM_SWZ(row * 128 + u * 16);
                CP_ASYNC16(stP + so,         ApP + (size_t)row * 512 + u * 8);
                CP_ASYNC16(stP + 16384 + so, BpP + (size_t)row * 512 + u * 8);
            }
            uint32_t a[2][4];
#pragma unroll
            for (int mt = 0; mt < 2; mt++) {
                int row = wm * 32 + mt * 16 + r8 + (sel & 1) * 8;
                int c16 = ks * 2 + (sel >> 1);
                ldmx4(a[mt][0], a[mt][1], a[mt][2], a[mt][3],
                      stA + SMEM_SWZ(row * 128 + c16 * 16));
            }
            uint32_t bq[4][2], bk[4][2];
#pragma unroll
            for (int gp = 0; gp < 2; gp++) {
                int c16 = ks * 2 + (sel & 1);
                int rowq = wn * 32 + gp * 16 + r8 + (sel >> 1) * 8;
                ldmx4(bq[gp*2][0], bq[gp*2][1], bq[gp*2+1][0], bq[gp*2+1][1],
                      stB + SMEM_SWZ(rowq * 128 + c16 * 16));
                int rowk = 64 + rowq;
                ldmx4(bk[gp*2][0], bk[gp*2][1], bk[gp*2+1][0], bk[gp*2+1][1],
                      stB + SMEM_SWZ(rowk * 128 + c16 * 16));
            }
#pragma unroll
            for (int mt = 0; mt < 2; mt++)
#pragma unroll
                for (int g = 0; g < 4; g++) {
                    mma_f16(c[mt][g],   a[mt], bq[g][0], bq[g][1]);
                    mma_f16(c[mt][4+g], a[mt], bk[g][0], bk[g][1]);
                }
        }
        if (pf) CP_COMMIT();

        if ((kc & 7) == 7) {
            const int h = kc >> 3;
            float* parr = (float*)(smem + (kc % 3) * KSTG);
#pragma unroll
            for (int mt = 0; mt < 2; mt++)
#pragma unroll
                for (int rh = 0; rh < 2; rh++) {
                    const int R = wm * 32 + mt * 16 + (lane >> 2) + rh * 8;
                    int gi = t * 128 + R;
                    const int e = lst[gi < cnt ? gi : cnt - 1];
                    const float* qrow = g_q + ((size_t)(b * Ll + (e & 255))) * Ee + h * 64;
                    const float* krow = g_k + ((size_t)(b * Ll + (e >> 8))) * Ee + h * 64;
                    float acc = 0.f;
#pragma unroll
                    for (int g = 0; g < 4; g++) {
                        const int d0 = wn * 32 + g * 8 + 2 * (lane & 3);
                        acc += (qrow[d0]     + c[mt][g][rh*2+0]) * (krow[d0]     + c[mt][4+g][rh*2+0]);
                        acc += (qrow[d0 + 1] + c[mt][g][rh*2+1]) * (krow[d0 + 1] + c[mt][4+g][rh*2+1]);
                    }
                    acc += __shfl_xor_sync(0xffffffffu, acc, 1);
                    acc += __shfl_xor_sync(0xffffffffu, acc, 2);
                    if ((lane & 3) == 0) parr[wn * 128 + R] = acc;
                }
            __syncthreads();
            if (tid < 128 && t * 128 + tid < cnt) {
                const int e = lst[t * 128 + tid];
                float lg = parr[tid] + parr[128 + tid];
                g_logits[((size_t)(b * Hh + h) * Ll + (e & 255)) * Ll + (e >> 8)] = lg;
            }
            __syncthreads();
#pragma unroll
            for (int mt = 0; mt < 2; mt++)
#pragma unroll
                for (int g = 0; g < 8; g++)
#pragma unroll
                    for (int e2 = 0; e2 < 4; e2++) c[mt][g][e2] = 0.f;
        }
    }
}

// ==================== fused softmax + PV (i-tile 32, occ 2) ====================
#define SPV_SMEM ((32*256 + 256*64) * 4)   // 96 KB
__global__ __launch_bounds__(256, 2)
void softpv_kernel(const int* __restrict__ adj, float* __restrict__ out_attn)
{
    extern __shared__ float sm[];
    float* Ws = sm;            // [32][256]
    float* Vs = sm + 32 * 256; // [256][64]
    int it = blockIdx.x, h = blockIdx.y, b = blockIdx.z;
    int i0 = it * 32;
    int tid = threadIdx.x, lane = tid & 31, w = tid >> 5;

    size_t lb = (((size_t)b * Hh + h) * Ll + i0) * Ll;
    const float4* lsrc = (const float4*)(g_logits + lb);
    float4* wdst = (float4*)Ws;
    for (int idx = tid; idx < 32 * 256 / 4; idx += 256) wdst[idx] = lsrc[idx];
    float4* vdst = (float4*)Vs;
    for (int idx = tid; idx < 256 * 64 / 4; idx += 256) {
        int jrow = idx >> 4, d4 = idx & 15;
        vdst[idx] = *(const float4*)(g_v + ((size_t)b * Ll + jrow) * Ee + h * 64 + d4 * 4);
    }
    __syncthreads();

    // softmax: 8 warps x 4 rows each
    for (int r = w * 4; r < w * 4 + 4; r++) {
        int i = i0 + r;
        const int* arow = adj + ((size_t)(b * Ll + i)) * Ll;
        float v[8]; bool msk[8];
        float mx = -CUDART_INF_F;
#pragma unroll
        for (int u = 0; u < 8; u++) {
            int j = lane + u * 32;
            msk[u] = (arow[j] == 1);
            v[u] = msk[u] ? -CUDART_INF_F : Ws[r * 256 + j];
            mx = fmaxf(mx, v[u]);
        }
#pragma unroll
        for (int o = 16; o > 0; o >>= 1) mx = fmaxf(mx, __shfl_xor_sync(0xffffffffu, mx, o));
        float s = 0.f;
#pragma unroll
        for (int u = 0; u < 8; u++) {
            v[u] = msk[u] ? 0.f : expf(v[u] - mx);
            s += v[u];
        }
#pragma unroll
        for (int o = 16; o > 0; o >>= 1) s += __shfl_xor_sync(0xffffffffu, s, o);
        float inv = 1.0f / s;
#pragma unroll
        for (int u = 0; u < 8; u++) {
            int j = lane + u * 32;
            float wgt = v[u] * inv;
            Ws[r * 256 + j] = wgt;
            out_attn[(((size_t)b * Ll + i) * Ll + j) * Hh + h] = wgt;
        }
    }
    __syncthreads();

    // PV: i = tid>>3 (0..31), 8 d's per thread
    int i = tid >> 3, t8 = tid & 7;
    float acc[8];
#pragma unroll
    for (int dd = 0; dd < 8; dd++) acc[dd] = 0.f;
    const float* wrow = Ws + i * 256;
    for (int jj = 0; jj < 256; jj += 4) {
        float4 wv = *(const float4*)(wrow + jj);
#pragma unroll
        for (int u = 0; u < 4; u++) {
            float wsc = (u == 0) ? wv.x : (u == 1) ? wv.y : (u == 2) ? wv.z : wv.w;
            const float* vr = Vs + (jj + u) * 64 + t8 * 8;
#pragma unroll
            for (int dd = 0; dd < 8; dd++) acc[dd] += wsc * vr[dd];
        }
    }
    float* op = g_o1 + ((size_t)b * Ll + i0 + i) * Ee + h * 64 + t8 * 8;
#pragma unroll
    for (int dd = 0; dd < 8; dd++) op[dd] = acc[dd];
}

// ==================== output GEMM (32x64 tiles, 128 blocks) ====================
__global__ __launch_bounds__(256)
void gemm_out_kernel(const float* __restrict__ X, const float* __restrict__ W,
                     const float* __restrict__ bias, float* __restrict__ Y)
{
    __shared__ float Xs[16][32];
    __shared__ float Ws[16][64];
    const int Kdim = Ee, Ndim = Ee;
    int m0 = blockIdx.y * 32, n0 = blockIdx.x * 64;
    int tid = threadIdx.x;
    int ty = tid >> 5, tx = tid & 31;       // 8 x 32: 4 rows x 2 cols each
    int rW = tid >> 2, c4 = tid & 3;        // W: 64 rows
    int rX = (tid & 127) >> 2;              // X: 32 rows (first 128 threads)
    bool ldx = tid < 128;

    float acc[4][2];
#pragma unroll
    for (int a = 0; a < 4; a++) { acc[a][0] = 0.f; acc[a][1] = 0.f; }

    float4 xv = ldx ? *(const float4*)(X + (size_t)(m0 + rX) * Kdim + c4 * 4)
                    : make_float4(0.f, 0.f, 0.f, 0.f);
    float4 wv = *(const float4*)(W + (size_t)(n0 + rW) * Kdim + c4 * 4);
    for (int kc = 0; kc < Kdim; kc += 16) {
        __syncthreads();
        if (ldx) {
            Xs[c4*4+0][rX]=xv.x; Xs[c4*4+1][rX]=xv.y; Xs[c4*4+2][rX]=xv.z; Xs[c4*4+3][rX]=xv.w;
        }
        Ws[c4*4+0][rW]=wv.x; Ws[c4*4+1][rW]=wv.y; Ws[c4*4+2][rW]=wv.z; Ws[c4*4+3][rW]=wv.w;
        __syncthreads();
        if (kc + 16 < Kdim) {
            if (ldx) xv = *(const float4*)(X + (size_t)(m0 + rX) * Kdim + kc + 16 + c4 * 4);
            wv = *(const float4*)(W + (size_t)(n0 + rW) * Kdim + kc + 16 + c4 * 4);
        }
#pragma unroll
        for (int cc = 0; cc < 16; cc++) {
            float4 a = *(const float4*)&Xs[cc][ty*4];
            float2 b2 = *(const float2*)&Ws[cc][tx*2];
            acc[0][0]+=a.x*b2.x; acc[0][1]+=a.x*b2.y;
            acc[1][0]+=a.y*b2.x; acc[1][1]+=a.y*b2.y;
            acc[2][0]+=a.z*b2.x; acc[2][1]+=a.z*b2.y;
            acc[3][0]+=a.w*b2.x; acc[3][1]+=a.w*b2.y;
        }
    }
#pragma unroll
    for (int rr = 0; rr < 4; rr++)
#pragma unroll
        for (int cc = 0; cc < 2; cc++)
            Y[(size_t)(m0+ty*4+rr) * Ndim + n0+tx*2+cc] = acc[rr][cc] + bias[n0+tx*2+cc];
}

// ---------------------------------------------------------------------------
extern "C" void kernel_launch(void* const* d_in, const int* in_sizes, int n_in,
                              void* d_out, int out_size)
{
    (void)in_sizes; (void)n_in; (void)out_size;
    const float* queries  = (const float*)d_in[0];
    const float* keys     = (const float*)d_in[1];
    const float* values   = (const float*)d_in[2];
    const float* relation = (const float*)d_in[3];
    const int*   adj      = (const int*)d_in[4];
    const float* Wq = (const float*)d_in[5];
    const float* bq = (const float*)d_in[6];
    const float* Wk = (const float*)d_in[7];
    const float* bk = (const float*)d_in[8];
    const float* Wv = (const float*)d_in[9];
    const float* bv = (const float*)d_in[10];
    const float* Wr = (const float*)d_in[11];
    const float* Wo = (const float*)d_in[12];
    const float* bo = (const float*)d_in[13];

    float* out      = (float*)d_out;
    float* out_attn = out + Bb * Ll * Ee;

    float *o1p; int *cntp;
    cudaGetSymbolAddress((void**)&o1p, g_o1);
    cudaGetSymbolAddress((void**)&cntp, g_cnt);

    cudaFuncSetAttribute(rel_attn_mma_kernel, cudaFuncAttributeMaxDynamicSharedMemorySize, MMA_SMEM);
    cudaFuncSetAttribute(softpv_kernel, cudaFuncAttributeMaxDynamicSharedMemorySize, SPV_SMEM);

    cudaMemsetAsync(cntp, 0, Bb * sizeof(int));
    pre_kernel<<<1216, 256>>>(Wr, adj, queries, keys, values,
                              Wq, bq, Wk, bk, Wv, bv);
    split_rel_gather_kernel<<<dim3(2048, Bb), 256>>>(relation);
    rel_attn_mma_kernel<<<dim3(512, Bb), 256, MMA_SMEM>>>();
    softpv_kernel<<<dim3(Ll / 32, Hh, Bb), 256, SPV_SMEM>>>(adj, out_attn);
    gemm_out_kernel<<<dim3(Ee/64, (Bb*Ll)/32), 256>>>(o1p, Wo, bo, out);
}

// round 17
// speedup vs baseline: 1.1150x; 1.0374x over previous
#include <cuda_runtime.h>
#include <cuda_fp16.h>
#include <cstdint>
#include <math_constants.h>

#define Bb 2
#define Ll 256
#define Ee 512
#define Hh 8
#define QSCALE 0.125f

// ---------------- device scratch ----------------
__device__ float g_q[Bb*Ll*Ee];
__device__ float g_k[Bb*Ll*Ee];
__device__ float g_v[Bb*Ll*Ee];
__device__ float g_logits[(size_t)Bb*Hh*Ll*Ll];
__device__ float g_o1[Bb*Ll*Ee];
__device__ __half g_rel_f16[(size_t)Bb*Ll*Ll*Ee];
__device__ __half g_w_f16[1024*512];   // [h*128+p][k]; p<64: Wrq rows, p>=64: Wrk rows
__device__ int g_cnt[Bb];
__device__ unsigned short g_list[Bb*Ll*Ll];

// ==================== PTX helpers ====================
__device__ __forceinline__ uint32_t smem_u32(const void* p) {
    uint32_t a;
    asm("{ .reg .u64 t; cvta.to.shared.u64 t, %1; cvt.u32.u64 %0, t; }" : "=r"(a) : "l"(p));
    return a;
}
#define SMEM_SWZ(o) ((o) ^ (((o) >> 3) & 0x70))
#define CP_ASYNC16(dst, src) \
    asm volatile("cp.async.cg.shared.global [%0], [%1], 16;" :: "r"(dst), "l"(src))
#define CP_COMMIT() asm volatile("cp.async.commit_group;" ::: "memory")
#define CP_WAIT1() asm volatile("cp.async.wait_group 1;" ::: "memory")
#define CP_WAIT0() asm volatile("cp.async.wait_group 0;" ::: "memory")

__device__ __forceinline__ void ldmx4(uint32_t& r0, uint32_t& r1, uint32_t& r2, uint32_t& r3, uint32_t addr) {
    asm volatile("ldmatrix.sync.aligned.m8n8.x4.shared.b16 {%0,%1,%2,%3}, [%4];"
        : "=r"(r0), "=r"(r1), "=r"(r2), "=r"(r3) : "r"(addr));
}
__device__ __forceinline__ void mma_f16(float* c, const uint32_t* a, uint32_t b0, uint32_t b1) {
    asm volatile("mma.sync.aligned.m16n8k16.row.col.f32.f16.f16.f32 "
        "{%0,%1,%2,%3}, {%4,%5,%6,%7}, {%8,%9}, {%0,%1,%2,%3};"
        : "+f"(c[0]), "+f"(c[1]), "+f"(c[2]), "+f"(c[3])
        : "r"(a[0]), "r"(a[1]), "r"(a[2]), "r"(a[3]), "r"(b0), "r"(b1));
}
__device__ __forceinline__ void cvt4_f16(float4 v, __half* dst) {
    __half2* d2 = (__half2*)dst;
    d2[0] = __floats2half2_rn(v.x, v.y);
    d2[1] = __floats2half2_rn(v.z, v.w);
}

// ==================== double-buffered fp32 GEMM body (qkv) ====================
__device__ __forceinline__ void gemm64_db(const float* __restrict__ X,
                                          const float* __restrict__ W,
                                          const float* __restrict__ bias,
                                          float* __restrict__ Y,
                                          int m0, int n0, int Kdim, int Ndim,
                                          float scale,
                                          float Xs[16][64], float Ws[16][64])
{
    int tid = threadIdx.x;
    int ty = tid >> 4, tx = tid & 15;
    int r = tid >> 2, c4 = tid & 3;
    float acc[4][4];
#pragma unroll
    for (int a = 0; a < 4; a++)
#pragma unroll
        for (int bb = 0; bb < 4; bb++) acc[a][bb] = 0.f;

    float4 xv = *(const float4*)(X + (size_t)(m0 + r) * Kdim + c4 * 4);
    float4 wv = *(const float4*)(W + (size_t)(n0 + r) * Kdim + c4 * 4);
    for (int kc = 0; kc < Kdim; kc += 16) {
        __syncthreads();
        Xs[c4*4+0][r]=xv.x; Xs[c4*4+1][r]=xv.y; Xs[c4*4+2][r]=xv.z; Xs[c4*4+3][r]=xv.w;
        Ws[c4*4+0][r]=wv.x; Ws[c4*4+1][r]=wv.y; Ws[c4*4+2][r]=wv.z; Ws[c4*4+3][r]=wv.w;
        __syncthreads();
        if (kc + 16 < Kdim) {
            xv = *(const float4*)(X + (size_t)(m0 + r) * Kdim + kc + 16 + c4 * 4);
            wv = *(const float4*)(W + (size_t)(n0 + r) * Kdim + kc + 16 + c4 * 4);
        }
#pragma unroll
        for (int cc = 0; cc < 16; cc++) {
            float4 a = *(const float4*)&Xs[cc][ty*4];
            float4 bv4 = *(const float4*)&Ws[cc][tx*4];
            acc[0][0]+=a.x*bv4.x; acc[0][1]+=a.x*bv4.y; acc[0][2]+=a.x*bv4.z; acc[0][3]+=a.x*bv4.w;
            acc[1][0]+=a.y*bv4.x; acc[1][1]+=a.y*bv4.y; acc[1][2]+=a.y*bv4.z; acc[1][3]+=a.y*bv4.w;
            acc[2][0]+=a.z*bv4.x; acc[2][1]+=a.z*bv4.y; acc[2][2]+=a.z*bv4.z; acc[2][3]+=a.z*bv4.w;
            acc[3][0]+=a.w*bv4.x; acc[3][1]+=a.w*bv4.y; acc[3][2]+=a.w*bv4.z; acc[3][3]+=a.w*bv4.w;
        }
    }
#pragma unroll
    for (int rr = 0; rr < 4; rr++)
#pragma unroll
        for (int cc = 0; cc < 4; cc++)
            Y[(size_t)(m0+ty*4+rr) * Ndim + n0+tx*4+cc] = (acc[rr][cc] + bias[n0+tx*4+cc]) * scale;
}

// ==================== merged pre-pass: W-split | compaction | qkv ====================
__global__ __launch_bounds__(256)
void pre_kernel(const float* __restrict__ Wr, const int* __restrict__ adj,
                const float* __restrict__ queries, const float* __restrict__ keys,
                const float* __restrict__ values,
                const float* __restrict__ Wq, const float* __restrict__ bq,
                const float* __restrict__ Wk, const float* __restrict__ bk,
                const float* __restrict__ Wv, const float* __restrict__ bv)
{
    const int bid = blockIdx.x;
    const int tid = threadIdx.x;
    if (bid < 512) {
        int r = bid * 2 + (tid >> 7);
        int h = r >> 7, p = r & 127;
        int in_row = (p < 64) ? (h*64 + p) : (512 + h*64 + (p - 64));
        int t = tid & 127;
        float4 v = ((const float4*)(Wr + (size_t)in_row * 512))[t];
        cvt4_f16(v, g_w_f16 + (size_t)r * 512 + t * 4);
        return;
    }
    if (bid < 1024) {
        int j = (bid - 512) & 255, b = (bid - 512) >> 8, i = tid;
        int lane = i & 31, w = i >> 5;
        bool keep = adj[((size_t)(b * Ll + i)) * Ll + j] != 1;
        unsigned m = __ballot_sync(0xffffffffu, keep);
        int wpos = __popc(m & ((1u << lane) - 1));
        __shared__ int wcnt[8], wbase[9];
        if (lane == 0) wcnt[w] = __popc(m);
        __syncthreads();
        if (i == 0) {
            int s = 0;
            for (int x = 0; x < 8; x++) { wbase[x] = s; s += wcnt[x]; }
            wbase[8] = atomicAdd(&g_cnt[b], s);
        }
        __syncthreads();
        if (keep) g_list[b * (Ll*Ll) + wbase[8] + wbase[w] + wpos] = (unsigned short)((j << 8) | i);
        return;
    }
    int bid2 = bid - 1024;
    int z = bid2 >> 6, rem = bid2 & 63;
    const float* X = (z == 0) ? queries : (z == 1) ? keys : values;
    const float* W = (z == 0) ? Wq : (z == 1) ? Wk : Wv;
    const float* bias = (z == 0) ? bq : (z == 1) ? bk : bv;
    float* Y = (z == 0) ? g_q : (z == 1) ? g_k : g_v;
    const float scale = (z == 0) ? QSCALE : 1.0f;

    __shared__ float Xs[16][64];
    __shared__ float Ws[16][64];
    gemm64_db(X, W, bias, Y, (rem >> 3) * 64, (rem & 7) * 64, Ee, Ee, scale, Xs, Ws);
}

// Gather + fp16-round ONLY unmasked rel rows; grid-stride.
__global__ __launch_bounds__(256)
void split_rel_gather_kernel(const float* __restrict__ rel) {
    int b = blockIdx.y;
    const int cnt = g_cnt[b];
    int t = threadIdx.x & 127;
    for (int ent = blockIdx.x * 2 + (threadIdx.x >> 7); ent < cnt; ent += gridDim.x * 2) {
        int e = g_list[b * (Ll*Ll) + ent];
        float4 v = ((const float4*)(rel + ((size_t)(b * (Ll*Ll)) + e) * 512))[t];
        cvt4_f16(v, g_rel_f16 + ((size_t)(b * (Ll*Ll)) + ent) * 512 + t * 4);
    }
}

// ==================== fp16 mma.sync relation attention (UNCHANGED) ====================
#define KSTG 32768
#define MMA_SMEM (3*KSTG)

__global__ void __launch_bounds__(256, 2) rel_attn_mma_kernel()
{
    extern __shared__ char smem[];
    const uint32_t sb = smem_u32(smem);
    const int tid = threadIdx.x, lane = tid & 31, w = tid >> 5;
    const int wm = w & 3, wn = w >> 2;
    const int t = blockIdx.x, b = blockIdx.y;

    const int cnt = g_cnt[b];
    if (t * 128 >= cnt) return;
    const size_t rbase = (size_t)(b * (Ll*Ll)) + t * 128;
    const unsigned short* lst = g_list + b * (Ll*Ll);

    float c[2][8][4];
#pragma unroll
    for (int mt = 0; mt < 2; mt++)
#pragma unroll
        for (int g = 0; g < 8; g++)
#pragma unroll
            for (int e = 0; e < 4; e++) c[mt][g][e] = 0.f;

    auto issue_full = [&](int kc) {
        const int h = kc >> 3;
        const int kcol = (kc & 7) * 64;
        const uint32_t st = sb + (kc % 3) * KSTG;
        const __half* Bp = g_w_f16 + (size_t)h * 128 * 512;
#pragma unroll
        for (int r4 = 0; r4 < 4; r4++) {
            int idx = tid + r4 * 256;
            int row = idx >> 3, u = idx & 7;
            uint32_t so = SMEM_SWZ(row * 128 + u * 16);
            CP_ASYNC16(st + so,         g_rel_f16 + (rbase + row) * 512 + kcol + u * 8);
            CP_ASYNC16(st + 16384 + so, Bp + (size_t)row * 512 + kcol + u * 8);
        }
        CP_COMMIT();
    };

    issue_full(0); issue_full(1);

    for (int kc = 0; kc < 64; kc++) {
        const bool pf = (kc + 2 < 64);
        if (pf) { CP_WAIT1(); } else { CP_WAIT0(); }
        __syncthreads();

        const int kp = kc + 2;
        const uint32_t stP = sb + (kp % 3) * KSTG;
        const __half* ApP = g_rel_f16 + rbase * 512 + ((kp & 7) * 64);
        const __half* BpP = g_w_f16 + (size_t)(kp >> 3) * 128 * 512 + ((kp & 7) * 64);

        const uint32_t stA = sb + (kc % 3) * KSTG;
        const uint32_t stB = stA + 16384;
        const int r8 = lane & 7, sel = lane >> 3;
#pragma unroll
        for (int ks = 0; ks < 4; ks++) {
            if (pf) {
                int idx = tid + ks * 256;
                int row = idx >> 3, u = idx & 7;
                uint32_t so = SMEM_SWZ(row * 128 + u * 16);
                CP_ASYNC16(stP + so,         ApP + (size_t)row * 512 + u * 8);
                CP_ASYNC16(stP + 16384 + so, BpP + (size_t)row * 512 + u * 8);
            }
            uint32_t a[2][4];
#pragma unroll
            for (int mt = 0; mt < 2; mt++) {
                int row = wm * 32 + mt * 16 + r8 + (sel & 1) * 8;
                int c16 = ks * 2 + (sel >> 1);
                ldmx4(a[mt][0], a[mt][1], a[mt][2], a[mt][3],
                      stA + SMEM_SWZ(row * 128 + c16 * 16));
            }
            uint32_t bq[4][2], bk[4][2];
#pragma unroll
            for (int gp = 0; gp < 2; gp++) {
                int c16 = ks * 2 + (sel & 1);
                int rowq = wn * 32 + gp * 16 + r8 + (sel >> 1) * 8;
                ldmx4(bq[gp*2][0], bq[gp*2][1], bq[gp*2+1][0], bq[gp*2+1][1],
                      stB + SMEM_SWZ(rowq * 128 + c16 * 16));
                int rowk = 64 + rowq;
                ldmx4(bk[gp*2][0], bk[gp*2][1], bk[gp*2+1][0], bk[gp*2+1][1],
                      stB + SMEM_SWZ(rowk * 128 + c16 * 16));
            }
#pragma unroll
            for (int mt = 0; mt < 2; mt++)
#pragma unroll
                for (int g = 0; g < 4; g++) {
                    mma_f16(c[mt][g],   a[mt], bq[g][0], bq[g][1]);
                    mma_f16(c[mt][4+g], a[mt], bk[g][0], bk[g][1]);
                }
        }
        if (pf) CP_COMMIT();

        if ((kc & 7) == 7) {
            const int h = kc >> 3;
            float* parr = (float*)(smem + (kc % 3) * KSTG);
#pragma unroll
            for (int mt = 0; mt < 2; mt++)
#pragma unroll
                for (int rh = 0; rh < 2; rh++) {
                    const int R = wm * 32 + mt * 16 + (lane >> 2) + rh * 8;
                    int gi = t * 128 + R;
                    const int e = lst[gi < cnt ? gi : cnt - 1];
                    const float* qrow = g_q + ((size_t)(b * Ll + (e & 255))) * Ee + h * 64;
                    const float* krow = g_k + ((size_t)(b * Ll + (e >> 8))) * Ee + h * 64;
                    float acc = 0.f;
#pragma unroll
                    for (int g = 0; g < 4; g++) {
                        const int d0 = wn * 32 + g * 8 + 2 * (lane & 3);
                        acc += (qrow[d0]     + c[mt][g][rh*2+0]) * (krow[d0]     + c[mt][4+g][rh*2+0]);
                        acc += (qrow[d0 + 1] + c[mt][g][rh*2+1]) * (krow[d0 + 1] + c[mt][4+g][rh*2+1]);
                    }
                    acc += __shfl_xor_sync(0xffffffffu, acc, 1);
                    acc += __shfl_xor_sync(0xffffffffu, acc, 2);
                    if ((lane & 3) == 0) parr[wn * 128 + R] = acc;
                }
            __syncthreads();
            if (tid < 128 && t * 128 + tid < cnt) {
                const int e = lst[t * 128 + tid];
                float lg = parr[tid] + parr[128 + tid];
                g_logits[((size_t)(b * Hh + h) * Ll + (e & 255)) * Ll + (e >> 8)] = lg;
            }
            __syncthreads();
#pragma unroll
            for (int mt = 0; mt < 2; mt++)
#pragma unroll
                for (int g = 0; g < 8; g++)
#pragma unroll
                    for (int e2 = 0; e2 < 4; e2++) c[mt][g][e2] = 0.f;
        }
    }
}

// ==================== fused softmax + PV (i-tile 16, 512 blocks) ====================
#define SPV_SMEM ((16*256 + 256*64) * 4)   // 80 KB
__global__ __launch_bounds__(256, 2)
void softpv_kernel(const int* __restrict__ adj, float* __restrict__ out_attn)
{
    extern __shared__ float sm[];
    float* Ws = sm;            // [16][256]
    float* Vs = sm + 16 * 256; // [256][64]
    int it = blockIdx.x, h = blockIdx.y, b = blockIdx.z;
    int i0 = it * 16;
    int tid = threadIdx.x, lane = tid & 31, w = tid >> 5;

    size_t lb = (((size_t)b * Hh + h) * Ll + i0) * Ll;
    const float4* lsrc = (const float4*)(g_logits + lb);
    float4* wdst = (float4*)Ws;
    for (int idx = tid; idx < 16 * 256 / 4; idx += 256) wdst[idx] = lsrc[idx];
    float4* vdst = (float4*)Vs;
    for (int idx = tid; idx < 256 * 64 / 4; idx += 256) {
        int jrow = idx >> 4, d4 = idx & 15;
        vdst[idx] = *(const float4*)(g_v + ((size_t)b * Ll + jrow) * Ee + h * 64 + d4 * 4);
    }
    __syncthreads();

    // softmax: 8 warps x 2 rows each
    for (int r = w * 2; r < w * 2 + 2; r++) {
        int i = i0 + r;
        const int* arow = adj + ((size_t)(b * Ll + i)) * Ll;
        float v[8]; bool msk[8];
        float mx = -CUDART_INF_F;
#pragma unroll
        for (int u = 0; u < 8; u++) {
            int j = lane + u * 32;
            msk[u] = (arow[j] == 1);
            v[u] = msk[u] ? -CUDART_INF_F : Ws[r * 256 + j];
            mx = fmaxf(mx, v[u]);
        }
#pragma unroll
        for (int o = 16; o > 0; o >>= 1) mx = fmaxf(mx, __shfl_xor_sync(0xffffffffu, mx, o));
        float s = 0.f;
#pragma unroll
        for (int u = 0; u < 8; u++) {
            v[u] = msk[u] ? 0.f : expf(v[u] - mx);
            s += v[u];
        }
#pragma unroll
        for (int o = 16; o > 0; o >>= 1) s += __shfl_xor_sync(0xffffffffu, s, o);
        float inv = 1.0f / s;
#pragma unroll
        for (int u = 0; u < 8; u++) {
            int j = lane + u * 32;
            float wgt = v[u] * inv;
            Ws[r * 256 + j] = wgt;
            out_attn[(((size_t)b * Ll + i) * Ll + j) * Hh + h] = wgt;
        }
    }
    __syncthreads();

    // PV: i = tid>>4 (0..15), 16 threads per row, 4 d's each
    int i = tid >> 4, t16 = tid & 15;
    float acc[4];
#pragma unroll
    for (int dd = 0; dd < 4; dd++) acc[dd] = 0.f;
    const float* wrow = Ws + i * 256;
    for (int jj = 0; jj < 256; jj += 4) {
        float4 wv = *(const float4*)(wrow + jj);
#pragma unroll
        for (int u = 0; u < 4; u++) {
            float wsc = (u == 0) ? wv.x : (u == 1) ? wv.y : (u == 2) ? wv.z : wv.w;
            const float* vr = Vs + (jj + u) * 64 + t16 * 4;
#pragma unroll
            for (int dd = 0; dd < 4; dd++) acc[dd] += wsc * vr[dd];
        }
    }
    float* op = g_o1 + ((size_t)b * Ll + i0 + i) * Ee + h * 64 + t16 * 4;
#pragma unroll
    for (int dd = 0; dd < 4; dd++) op[dd] = acc[dd];
}

// ==================== output GEMM (32x32 tiles, 256 blocks) ====================
__global__ __launch_bounds__(256)
void gemm_out_kernel(const float* __restrict__ X, const float* __restrict__ W,
                     const float* __restrict__ bias, float* __restrict__ Y)
{
    __shared__ float Xs[16][32];
    __shared__ float Ws[16][32];
    const int Kdim = Ee, Ndim = Ee;
    int m0 = blockIdx.y * 32, n0 = blockIdx.x * 32;
    int tid = threadIdx.x;
    int ty = tid >> 5, tx = tid & 31;       // 8 x 32: 4 rows x 1 col each
    int rL = (tid & 127) >> 2, c4 = tid & 3;
    bool isX = tid < 128;

    float acc[4];
#pragma unroll
    for (int a = 0; a < 4; a++) acc[a] = 0.f;

    const float* Lsrc = isX ? X : W;
    int lrow0 = isX ? m0 : n0;
    float4 lv = *(const float4*)(Lsrc + (size_t)(lrow0 + rL) * Kdim + c4 * 4);
    for (int kc = 0; kc < Kdim; kc += 16) {
        __syncthreads();
        if (isX) {
            Xs[c4*4+0][rL]=lv.x; Xs[c4*4+1][rL]=lv.y; Xs[c4*4+2][rL]=lv.z; Xs[c4*4+3][rL]=lv.w;
        } else {
            Ws[c4*4+0][rL]=lv.x; Ws[c4*4+1][rL]=lv.y; Ws[c4*4+2][rL]=lv.z; Ws[c4*4+3][rL]=lv.w;
        }
        __syncthreads();
        if (kc + 16 < Kdim)
            lv = *(const float4*)(Lsrc + (size_t)(lrow0 + rL) * Kdim + kc + 16 + c4 * 4);
#pragma unroll
        for (int cc = 0; cc < 16; cc++) {
            float4 a = *(const float4*)&Xs[cc][ty*4];
            float bw = Ws[cc][tx];
            acc[0] += a.x * bw;
            acc[1] += a.y * bw;
            acc[2] += a.z * bw;
            acc[3] += a.w * bw;
        }
    }
#pragma unroll
    for (int rr = 0; rr < 4; rr++)
        Y[(size_t)(m0+ty*4+rr) * Ndim + n0+tx] = acc[rr] + bias[n0+tx];
}

// ---------------------------------------------------------------------------
extern "C" void kernel_launch(void* const* d_in, const int* in_sizes, int n_in,
                              void* d_out, int out_size)
{
    (void)in_sizes; (void)n_in; (void)out_size;
    const float* queries  = (const float*)d_in[0];
    const float* keys     = (const float*)d_in[1];
    const float* values   = (const float*)d_in[2];
    const float* relation = (const float*)d_in[3];
    const int*   adj      = (const int*)d_in[4];
    const float* Wq = (const float*)d_in[5];
    const float* bq = (const float*)d_in[6];
    const float* Wk = (const float*)d_in[7];
    const float* bk = (const float*)d_in[8];
    const float* Wv = (const float*)d_in[9];
    const float* bv = (const float*)d_in[10];
    const float* Wr = (const float*)d_in[11];
    const float* Wo = (const float*)d_in[12];
    const float* bo = (const float*)d_in[13];

    float* out      = (float*)d_out;
    float* out_attn = out + Bb * Ll * Ee;

    float *o1p; int *cntp;
    cudaGetSymbolAddress((void**)&o1p, g_o1);
    cudaGetSymbolAddress((void**)&cntp, g_cnt);

    cudaFuncSetAttribute(rel_attn_mma_kernel, cudaFuncAttributeMaxDynamicSharedMemorySize, MMA_SMEM);
    cudaFuncSetAttribute(softpv_kernel, cudaFuncAttributeMaxDynamicSharedMemorySize, SPV_SMEM);

    cudaMemsetAsync(cntp, 0, Bb * sizeof(int));
    pre_kernel<<<1216, 256>>>(Wr, adj, queries, keys, values,
                              Wq, bq, Wk, bk, Wv, bv);
    split_rel_gather_kernel<<<dim3(2048, Bb), 256>>>(relation);
    rel_attn_mma_kernel<<<dim3(512, Bb), 256, MMA_SMEM>>>();
    softpv_kernel<<<dim3(Ll / 16, Hh, Bb), 256, SPV_SMEM>>>(adj, out_attn);
    gemm_out_kernel<<<dim3(Ee/32, (Bb*Ll)/32), 256>>>(o1p, Wo, bo, out);
}